// round 1
// baseline (speedup 1.0000x reference)
#include <cuda_runtime.h>
#include <cstdint>

#define B_    2
#define S_    2048
#define HID   2048
#define NH    32
#define HD    64
#define QC    1024
#define KVC   512
#define SCALE_ 0.125f

// Scratch (allocation-free: __device__ globals)
__device__ float g_comp[(size_t)B_ * S_ * HID];   // [B*S, 2048] compressed
__device__ float g_q[(size_t)B_ * S_ * HID];      // [B, H, S, D]
__device__ float g_k[(size_t)B_ * S_ * HID];      // [B, H, S, D]
__device__ float g_v[(size_t)B_ * S_ * HID];      // [B, H, S, D]
__device__ float g_attn[(size_t)B_ * S_ * HID];   // [B*S, HID]

// ---------------------------------------------------------------------------
// Generic fp32 GEMM: C[M,N] = A[M,K(lda)] * B[K,N(ldb)], row-major.
// BM=BN=128, BK=16, 256 threads, 8x8 microtile (split 4+4 for conflict-free smem).
// mode 0: C row-major [M,N] (ld = N)
// mode 1: scatter to [B, H, S, D]: r=(b,s), c=(h,d)
// All dims are multiples of tile sizes for this problem: no bounds checks.
// ---------------------------------------------------------------------------
__global__ __launch_bounds__(256) void sgemm_k(
    const float* __restrict__ A, int lda,
    const float* __restrict__ B, int ldb,
    float* __restrict__ C, int N, int K, int mode)
{
    __shared__ float As[16][128];  // transposed A tile: As[k][m]
    __shared__ float Bs[16][128];  // natural B tile:    Bs[k][n]

    const int tid  = threadIdx.x;
    const int tx   = tid & 15;
    const int ty   = tid >> 4;
    const int row0 = blockIdx.y * 128;
    const int col0 = blockIdx.x * 128;

    float acc[8][8];
#pragma unroll
    for (int i = 0; i < 8; i++)
#pragma unroll
        for (int j = 0; j < 8; j++) acc[i][j] = 0.f;

    const int arow = tid >> 2;          // 0..63
    const int acol = (tid & 3) << 2;    // 0,4,8,12
    const int brow = tid >> 5;          // 0..7
    const int bcol = (tid & 31) << 2;   // 0..124

    const float* Ap0 = A + (size_t)(row0 + arow) * lda + acol;
    const float* Ap1 = A + (size_t)(row0 + arow + 64) * lda + acol;
    const float* Bp0 = B + (size_t)brow * ldb + col0 + bcol;
    const float* Bp1 = B + (size_t)(brow + 8) * ldb + col0 + bcol;

    for (int k0 = 0; k0 < K; k0 += 16) {
        float4 a0 = *(const float4*)(Ap0 + k0);
        float4 a1 = *(const float4*)(Ap1 + k0);
        float4 b0 = *(const float4*)(Bp0 + (size_t)k0 * ldb);
        float4 b1 = *(const float4*)(Bp1 + (size_t)k0 * ldb);

        As[acol + 0][arow] = a0.x;  As[acol + 1][arow] = a0.y;
        As[acol + 2][arow] = a0.z;  As[acol + 3][arow] = a0.w;
        As[acol + 0][arow + 64] = a1.x;  As[acol + 1][arow + 64] = a1.y;
        As[acol + 2][arow + 64] = a1.z;  As[acol + 3][arow + 64] = a1.w;
        *(float4*)&Bs[brow][bcol]     = b0;
        *(float4*)&Bs[brow + 8][bcol] = b1;
        __syncthreads();

#pragma unroll
        for (int k = 0; k < 16; k++) {
            float af[8], bf[8];
#pragma unroll
            for (int i = 0; i < 4; i++) {
                af[i]     = As[k][ty * 4 + i];
                af[4 + i] = As[k][64 + ty * 4 + i];
                bf[i]     = Bs[k][tx * 4 + i];
                bf[4 + i] = Bs[k][64 + tx * 4 + i];
            }
#pragma unroll
            for (int i = 0; i < 8; i++)
#pragma unroll
                for (int j = 0; j < 8; j++)
                    acc[i][j] += af[i] * bf[j];
        }
        __syncthreads();
    }

#pragma unroll
    for (int i = 0; i < 8; i++) {
        const int r = row0 + ((i < 4) ? (ty * 4 + i) : (64 + ty * 4 + i - 4));
#pragma unroll
        for (int j = 0; j < 8; j++) {
            const int c = col0 + ((j < 4) ? (tx * 4 + j) : (64 + tx * 4 + j - 4));
            const float v = acc[i][j];
            if (mode == 0) {
                C[(size_t)r * N + c] = v;
            } else {
                const int b = r >> 11, s = r & 2047;
                const int h = c >> 6,  d = c & 63;
                C[(((size_t)b * NH + h) * S_ + s) * HD + d] = v;
            }
        }
    }
}

// ---------------------------------------------------------------------------
// Causal flash attention, fp32. One block per (q-tile 64, head, batch).
// 256 threads; 4x4 microtiles for both S = Q·K^T and O += P·V.
// Q/K/V in [B,H,S,D]; output written directly to [B,S,H*D].
// Dynamic smem: Qs/Ks/Vs/Ps, each [64][65] floats = 66,560 B total.
// ---------------------------------------------------------------------------
__global__ __launch_bounds__(256) void attn_k(
    const float* __restrict__ Q, const float* __restrict__ K,
    const float* __restrict__ V, float* __restrict__ Out)
{
    extern __shared__ float sm[];
    float* Qs = sm;               // [d][r], pitch 65
    float* Ks = sm + 64 * 65;     // [d][c], pitch 65
    float* Vs = sm + 2 * 64 * 65; // [k][d], pitch 65
    float* Ps = sm + 3 * 64 * 65; // [k][r], pitch 65

    const int tid = threadIdx.x;
    const int tx  = tid & 15;
    const int ty  = tid >> 4;
    const int qt  = blockIdx.x;
    const int h   = blockIdx.y;
    const int b   = blockIdx.z;
    const size_t base = ((size_t)b * NH + h) * S_ * HD;
    const float* Qb = Q + base;
    const float* Kb = K + base;
    const float* Vb = V + base;
    const int q0 = qt * 64;

    // Load Q tile transposed: Qs[d][r]
#pragma unroll
    for (int it = 0; it < 4; it++) {
        const int idx = tid + it * 256;
        const int r   = idx >> 4;
        const int c4  = (idx & 15) << 2;
        const float4 qv = *(const float4*)(Qb + (size_t)(q0 + r) * HD + c4);
        Qs[(c4 + 0) * 65 + r] = qv.x;  Qs[(c4 + 1) * 65 + r] = qv.y;
        Qs[(c4 + 2) * 65 + r] = qv.z;  Qs[(c4 + 3) * 65 + r] = qv.w;
    }

    float m_i[4], l_i[4], o[4][4];
#pragma unroll
    for (int i = 0; i < 4; i++) {
        m_i[i] = -1e30f;
        l_i[i] = 0.f;
#pragma unroll
        for (int j = 0; j < 4; j++) o[i][j] = 0.f;
    }

    for (int kt = 0; kt <= qt; kt++) {
        __syncthreads();  // prior iter's Ks/Vs/Ps consumers done (also fences Q load, iter 0)

        // Load K tile transposed + V tile natural
#pragma unroll
        for (int it = 0; it < 4; it++) {
            const int idx = tid + it * 256;
            const int r   = idx >> 4;
            const int c4  = (idx & 15) << 2;
            const float4 kv = *(const float4*)(Kb + (size_t)(kt * 64 + r) * HD + c4);
            Ks[(c4 + 0) * 65 + r] = kv.x;  Ks[(c4 + 1) * 65 + r] = kv.y;
            Ks[(c4 + 2) * 65 + r] = kv.z;  Ks[(c4 + 3) * 65 + r] = kv.w;
            const float4 vv = *(const float4*)(Vb + (size_t)(kt * 64 + r) * HD + c4);
            Vs[r * 65 + c4 + 0] = vv.x;  Vs[r * 65 + c4 + 1] = vv.y;
            Vs[r * 65 + c4 + 2] = vv.z;  Vs[r * 65 + c4 + 3] = vv.w;
        }
        __syncthreads();

        // S = Q · K^T  (64x64 tile, this thread: rows ty*4+i, cols tx*4+j)
        float s[4][4];
#pragma unroll
        for (int i = 0; i < 4; i++)
#pragma unroll
            for (int j = 0; j < 4; j++) s[i][j] = 0.f;

#pragma unroll 8
        for (int d = 0; d < 64; d++) {
            float qf[4], kf[4];
#pragma unroll
            for (int i = 0; i < 4; i++) qf[i] = Qs[d * 65 + ty * 4 + i];
#pragma unroll
            for (int j = 0; j < 4; j++) kf[j] = Ks[d * 65 + tx * 4 + j];
#pragma unroll
            for (int i = 0; i < 4; i++)
#pragma unroll
                for (int j = 0; j < 4; j++)
                    s[i][j] += qf[i] * kf[j];
        }

        // Scale + causal mask (diagonal tile: col>row -> -inf)
        if (kt == qt) {
#pragma unroll
            for (int i = 0; i < 4; i++)
#pragma unroll
                for (int j = 0; j < 4; j++)
                    s[i][j] = (tx * 4 + j > ty * 4 + i) ? -1e30f : s[i][j] * SCALE_;
        } else {
#pragma unroll
            for (int i = 0; i < 4; i++)
#pragma unroll
                for (int j = 0; j < 4; j++)
                    s[i][j] *= SCALE_;
        }

        // Online softmax (row reductions across the 16-lane tx-group)
#pragma unroll
        for (int i = 0; i < 4; i++) {
            float mx = fmaxf(fmaxf(s[i][0], s[i][1]), fmaxf(s[i][2], s[i][3]));
#pragma unroll
            for (int off = 1; off < 16; off <<= 1)
                mx = fmaxf(mx, __shfl_xor_sync(0xffffffffu, mx, off));
            const float mnew  = fmaxf(m_i[i], mx);
            const float alpha = __expf(m_i[i] - mnew);
            m_i[i] = mnew;
            float sum = 0.f;
#pragma unroll
            for (int j = 0; j < 4; j++) {
                const float p = __expf(s[i][j] - mnew);
                s[i][j] = p;
                sum += p;
            }
#pragma unroll
            for (int off = 1; off < 16; off <<= 1)
                sum += __shfl_xor_sync(0xffffffffu, sum, off);
            l_i[i] = l_i[i] * alpha + sum;
#pragma unroll
            for (int j = 0; j < 4; j++) o[i][j] *= alpha;
        }

        // Stage P (k-major) for the second GEMM
#pragma unroll
        for (int i = 0; i < 4; i++)
#pragma unroll
            for (int j = 0; j < 4; j++)
                Ps[(tx * 4 + j) * 65 + ty * 4 + i] = s[i][j];
        __syncthreads();

        // O += P · V (this thread: rows ty*4+i, d-cols tx*4+j)
#pragma unroll 8
        for (int kk = 0; kk < 64; kk++) {
            float pf[4], vf[4];
#pragma unroll
            for (int i = 0; i < 4; i++) pf[i] = Ps[kk * 65 + ty * 4 + i];
#pragma unroll
            for (int j = 0; j < 4; j++) vf[j] = Vs[kk * 65 + tx * 4 + j];
#pragma unroll
            for (int i = 0; i < 4; i++)
#pragma unroll
                for (int j = 0; j < 4; j++)
                    o[i][j] += pf[i] * vf[j];
        }
    }

    // Normalize + write to [B, S, H*D]
#pragma unroll
    for (int i = 0; i < 4; i++) {
        const float inv = 1.f / l_i[i];
        const int srow = q0 + ty * 4 + i;
#pragma unroll
        for (int j = 0; j < 4; j++) {
            Out[((size_t)b * S_ + srow) * HID + h * HD + tx * 4 + j] = o[i][j] * inv;
        }
    }
}

// ---------------------------------------------------------------------------
// Launch: 6 kernels, stream-ordered, graph-capturable, allocation-free.
// ---------------------------------------------------------------------------
extern "C" void kernel_launch(void* const* d_in, const int* in_sizes, int n_in,
                              void* d_out, int out_size)
{
    const float* hidden = (const float*)d_in[0];  // [2,2048,2048]
    const float* w_down = (const float*)d_in[1];  // [2048, 2048]
    const float* w_q_up = (const float*)d_in[2];  // [1024, 2048]
    const float* w_k_up = (const float*)d_in[3];  // [512, 2048]
    const float* w_v_up = (const float*)d_in[4];  // [512, 2048]
    const float* w_out  = (const float*)d_in[5];  // [2048, 2048]
    float* out = (float*)d_out;                   // [2,2048,2048]

    float *comp, *q, *k, *v, *attn;
    cudaGetSymbolAddress((void**)&comp, g_comp);
    cudaGetSymbolAddress((void**)&q,    g_q);
    cudaGetSymbolAddress((void**)&k,    g_k);
    cudaGetSymbolAddress((void**)&v,    g_v);
    cudaGetSymbolAddress((void**)&attn, g_attn);

    const int ATTN_SMEM = 4 * 64 * 65 * (int)sizeof(float);  // 66,560 B
    cudaFuncSetAttribute(attn_k, cudaFuncAttributeMaxDynamicSharedMemorySize, ATTN_SMEM);

    const dim3 gemm_grid(HID / 128, (B_ * S_) / 128);  // (16, 32)
    const dim3 blk(256);

    // 1) comp = hidden @ w_down                      [4096,2048] x [2048,2048]
    sgemm_k<<<gemm_grid, blk>>>(hidden, HID, w_down, HID, comp, HID, HID, 0);
    // 2) Q = q_c @ w_q_up  -> [B,H,S,D]              [4096,1024] x [1024,2048]
    sgemm_k<<<gemm_grid, blk>>>(comp, HID, w_q_up, HID, q, HID, QC, 1);
    // 3) K = k_c @ w_k_up  -> [B,H,S,D]              [4096, 512] x [ 512,2048]
    sgemm_k<<<gemm_grid, blk>>>(comp + QC, HID, w_k_up, HID, k, HID, KVC, 1);
    // 4) V = v_c @ w_v_up  -> [B,H,S,D]              [4096, 512] x [ 512,2048]
    sgemm_k<<<gemm_grid, blk>>>(comp + QC + KVC, HID, w_v_up, HID, v, HID, KVC, 1);
    // 5) causal flash attention -> [B,S,HID]
    attn_k<<<dim3(S_ / 64, NH, B_), blk, ATTN_SMEM>>>(q, k, v, attn);
    // 6) out = attn @ w_out                          [4096,2048] x [2048,2048]
    sgemm_k<<<gemm_grid, blk>>>(attn, HID, w_out, HID, out, HID, HID, 0);
}

// round 3
// speedup vs baseline: 1.4670x; 1.4670x over previous
#include <cuda_runtime.h>
#include <cuda_bf16.h>
#include <cstdint>

#define B_    2
#define S_    2048
#define HID   2048
#define NH    32
#define HD    64
#define QC    1024
#define KVC   512
#define SCALE_ 0.125f
#define MTOT  (B_ * S_)   // 4096

// ---------------------------------------------------------------------------
// Scratch (allocation-free: __device__ globals)
// ---------------------------------------------------------------------------
__device__ float g_comp[(size_t)MTOT * HID];
__device__ float g_q[(size_t)MTOT * HID];      // [B,H,S,D]
__device__ float g_k[(size_t)MTOT * HID];
__device__ float g_v[(size_t)MTOT * HID];
__device__ float g_attn[(size_t)MTOT * HID];   // [B*S, HID]
__device__ __align__(16) __nv_bfloat16 g_ahi[(size_t)MTOT * HID];
__device__ __align__(16) __nv_bfloat16 g_alo[(size_t)MTOT * HID];
__device__ __align__(16) __nv_bfloat16 g_bhi[(size_t)HID * HID];   // [N,K] (K-major)
__device__ __align__(16) __nv_bfloat16 g_blo[(size_t)HID * HID];

// ---------------------------------------------------------------------------
// PTX helpers (base sm_100-safe: mma.sync / ldmatrix / cp.async only)
// ---------------------------------------------------------------------------
__device__ __forceinline__ uint32_t smem_u32(const void* p) {
    uint32_t a;
    asm("{ .reg .u64 t; cvta.to.shared.u64 t, %1; cvt.u32.u64 %0, t; }" : "=r"(a) : "l"(p));
    return a;
}
__device__ __forceinline__ void ldmx4(uint32_t* r, uint32_t addr) {
    asm volatile("ldmatrix.sync.aligned.m8n8.x4.shared.b16 {%0,%1,%2,%3}, [%4];"
                 : "=r"(r[0]), "=r"(r[1]), "=r"(r[2]), "=r"(r[3]) : "r"(addr));
}
__device__ __forceinline__ void mma16816(float* d, const uint32_t* a, uint32_t b0, uint32_t b1) {
    asm volatile(
        "mma.sync.aligned.m16n8k16.row.col.f32.bf16.bf16.f32 "
        "{%0,%1,%2,%3}, {%4,%5,%6,%7}, {%8,%9}, {%0,%1,%2,%3};"
        : "+f"(d[0]), "+f"(d[1]), "+f"(d[2]), "+f"(d[3])
        : "r"(a[0]), "r"(a[1]), "r"(a[2]), "r"(a[3]), "r"(b0), "r"(b1));
}
#define CP_ASYNC16(dst, src) \
    asm volatile("cp.async.cg.shared.global [%0], [%1], 16;" :: "r"(dst), "l"(src))
#define CP_COMMIT() asm volatile("cp.async.commit_group;" ::: "memory")
#define CP_WAIT(n)  asm volatile("cp.async.wait_group %0;" :: "n"(n) : "memory")

// ---------------------------------------------------------------------------
// Split fp32 -> bf16 hi/lo, packed [MTOT, C] from src with row stride ld.
// ---------------------------------------------------------------------------
__global__ void split_a_k(const float* __restrict__ src, int ld, int C,
                          __nv_bfloat16* __restrict__ hi, __nv_bfloat16* __restrict__ lo)
{
    const int total = MTOT * (C >> 2);
    for (int idx = blockIdx.x * blockDim.x + threadIdx.x; idx < total;
         idx += gridDim.x * blockDim.x) {
        const int row = idx / (C >> 2);
        const int c4  = (idx - row * (C >> 2)) << 2;
        const float4 v = *(const float4*)(src + (size_t)row * ld + c4);
        float x[4] = {v.x, v.y, v.z, v.w};
        uint32_t ph[2], pl[2];
#pragma unroll
        for (int p = 0; p < 2; p++) {
            __nv_bfloat16 h0 = __float2bfloat16(x[p * 2 + 0]);
            __nv_bfloat16 h1 = __float2bfloat16(x[p * 2 + 1]);
            __nv_bfloat16 l0 = __float2bfloat16(x[p * 2 + 0] - __bfloat162float(h0));
            __nv_bfloat16 l1 = __float2bfloat16(x[p * 2 + 1] - __bfloat162float(h1));
            ph[p] = (uint32_t)__bfloat16_as_ushort(h0) | ((uint32_t)__bfloat16_as_ushort(h1) << 16);
            pl[p] = (uint32_t)__bfloat16_as_ushort(l0) | ((uint32_t)__bfloat16_as_ushort(l1) << 16);
        }
        *(uint2*)(hi + (size_t)row * C + c4) = make_uint2(ph[0], ph[1]);
        *(uint2*)(lo + (size_t)row * C + c4) = make_uint2(pl[0], pl[1]);
    }
}

// ---------------------------------------------------------------------------
// Weight transpose + split: W[K,N] fp32 -> Wt hi/lo [N,K] bf16.
// ---------------------------------------------------------------------------
__global__ void wsplitT_k(const float* __restrict__ W, int K, int N,
                          __nv_bfloat16* __restrict__ hi, __nv_bfloat16* __restrict__ lo)
{
    __shared__ float tile[32][33];
    const int n0 = blockIdx.x * 32;
    const int k0 = blockIdx.y * 32;
    const int tx = threadIdx.x, ty = threadIdx.y;
#pragma unroll
    for (int i = 0; i < 4; i++)
        tile[ty + i * 8][tx] = W[(size_t)(k0 + ty + i * 8) * N + n0 + tx];
    __syncthreads();
#pragma unroll
    for (int i = 0; i < 4; i++) {
        const float x = tile[tx][ty + i * 8];
        const __nv_bfloat16 h = __float2bfloat16(x);
        const __nv_bfloat16 l = __float2bfloat16(x - __bfloat162float(h));
        const size_t o = (size_t)(n0 + ty + i * 8) * K + k0 + tx;
        hi[o] = h;
        lo[o] = l;
    }
}

// ---------------------------------------------------------------------------
// mma.sync bf16 split-3-pass GEMM.
// C[MTOT, 2048] = Ahi*Bhi^T + Ahi*Blo^T + Alo*Bhi^T  (fp32 accum)
// 128x128 tile, BK=32, 256 thr (8 warps: warp_m=wid&3 -> 32 rows,
// warp_n=wid>>2 -> 64 cols). cp.async double-buffered. K-major smem, pitch 80B.
// mode 0: C row-major [M,2048];  mode 1: scatter to [B,H,S,D].
// ---------------------------------------------------------------------------
#define PITCH     80
#define MAT_BYTES (128 * PITCH)          // 10240
#define STAGE_BYTES (4 * MAT_BYTES)      // 40960: Ahi | Alo | Bhi | Blo
#define GEMM_SMEM (2 * STAGE_BYTES)      // 81920

__global__ __launch_bounds__(256, 1) void tc_gemm_k(
    const __nv_bfloat16* __restrict__ Ahi, const __nv_bfloat16* __restrict__ Alo,
    const __nv_bfloat16* __restrict__ Bhi, const __nv_bfloat16* __restrict__ Blo,
    float* __restrict__ C, int K, int mode)
{
    extern __shared__ char smem[];
    const uint32_t sb = smem_u32(smem);
    const int tid = threadIdx.x;
    const int wid = tid >> 5;
    const int lid = tid & 31;
    const int warp_m = wid & 3;          // 32-row band
    const int warp_n = wid >> 2;         // 64-col band
    const int row0 = blockIdx.y * 128;
    const int col0 = blockIdx.x * 128;
    const int NC = K >> 5;               // number of 32-wide K chunks

    float acc[2][8][4];
#pragma unroll
    for (int i = 0; i < 2; i++)
#pragma unroll
        for (int j = 0; j < 8; j++)
#pragma unroll
            for (int t = 0; t < 4; t++) acc[i][j][t] = 0.f;

    // ---- async loader: 128 rows x 64B per matrix; thread handles 2 segs/matrix
    auto load_chunk = [&](int kc, int stage) {
        const uint32_t base = sb + stage * STAGE_BYTES;
        const int kel = kc * 32;
#pragma unroll
        for (int i = 0; i < 2; i++) {
            const int seg = tid + i * 256;       // 0..511
            const int row = seg >> 2;
            const int s16 = seg & 3;
            const uint32_t so = (uint32_t)(row * PITCH + s16 * 16);
            const size_t ga = (size_t)(row0 + row) * K + kel + s16 * 8;
            const size_t gb = (size_t)(col0 + row) * K + kel + s16 * 8;
            CP_ASYNC16(base + so,                  (const char*)(Ahi + ga));
            CP_ASYNC16(base + MAT_BYTES + so,      (const char*)(Alo + ga));
            CP_ASYNC16(base + 2 * MAT_BYTES + so,  (const char*)(Bhi + gb));
            CP_ASYNC16(base + 3 * MAT_BYTES + so,  (const char*)(Blo + gb));
        }
    };

    load_chunk(0, 0);
    CP_COMMIT();

    for (int c = 0; c < NC; c++) {
        if (c + 1 < NC) { load_chunk(c + 1, (c + 1) & 1); CP_COMMIT(); CP_WAIT(1); }
        else            { CP_WAIT(0); }
        __syncthreads();

        const uint32_t st = sb + (c & 1) * STAGE_BYTES;
        const uint32_t sAh = st;
        const uint32_t sAl = st + MAT_BYTES;
        const uint32_t sBh = st + 2 * MAT_BYTES;
        const uint32_t sBl = st + 3 * MAT_BYTES;

#pragma unroll
        for (int s = 0; s < 2; s++) {            // two k16 steps
            uint32_t ah[2][4], al[2][4];
            {
                const int kb = s * 32 + (lid >> 4) * 16;
#pragma unroll
                for (int mf = 0; mf < 2; mf++) {
                    const int row = warp_m * 32 + mf * 16 + (lid & 15);
                    ldmx4(ah[mf], sAh + row * PITCH + kb);
                    ldmx4(al[mf], sAl + row * PITCH + kb);
                }
            }
            uint32_t bh[4][4], bl[4][4];
            {
                const int kb = s * 32 + ((lid >> 3) & 1) * 16;
                const int nl = (lid & 7) + ((lid >> 4) & 1) * 8;
#pragma unroll
                for (int nf4 = 0; nf4 < 4; nf4++) {
                    const int n = warp_n * 64 + nf4 * 16 + nl;
                    ldmx4(bh[nf4], sBh + n * PITCH + kb);
                    ldmx4(bl[nf4], sBl + n * PITCH + kb);
                }
            }
#pragma unroll
            for (int mf = 0; mf < 2; mf++)
#pragma unroll
                for (int nf4 = 0; nf4 < 4; nf4++)
#pragma unroll
                    for (int h = 0; h < 2; h++) {
                        float* d = acc[mf][nf4 * 2 + h];
                        mma16816(d, ah[mf], bh[nf4][h * 2], bh[nf4][h * 2 + 1]);
                        mma16816(d, ah[mf], bl[nf4][h * 2], bl[nf4][h * 2 + 1]);
                        mma16816(d, al[mf], bh[nf4][h * 2], bh[nf4][h * 2 + 1]);
                    }
        }
        __syncthreads();
    }

    // ---- epilogue: registers -> global
#pragma unroll
    for (int mf = 0; mf < 2; mf++) {
        const int rbase = row0 + warp_m * 32 + mf * 16 + (lid >> 2);
#pragma unroll
        for (int nf = 0; nf < 8; nf++) {
            const int cidx = col0 + warp_n * 64 + nf * 8 + (lid & 3) * 2;
#pragma unroll
            for (int half = 0; half < 2; half++) {
                const int r = rbase + half * 8;
                const float2 val = make_float2(acc[mf][nf][half * 2], acc[mf][nf][half * 2 + 1]);
                if (mode == 0) {
                    *(float2*)(C + (size_t)r * HID + cidx) = val;
                } else {
                    const int bb = r >> 11, srow = r & 2047;
                    const int h = cidx >> 6, dd = cidx & 63;
                    *(float2*)(C + (((size_t)bb * NH + h) * S_ + srow) * HD + dd) = val;
                }
            }
        }
    }
}

// ---------------------------------------------------------------------------
// Causal flash attention, fp32 (unchanged from R1 — passed at rel_err 1.4e-6).
// ---------------------------------------------------------------------------
__global__ __launch_bounds__(256) void attn_k(
    const float* __restrict__ Q, const float* __restrict__ K,
    const float* __restrict__ V, float* __restrict__ Out)
{
    extern __shared__ float sm[];
    float* Qs = sm;
    float* Ks = sm + 64 * 65;
    float* Vs = sm + 2 * 64 * 65;
    float* Ps = sm + 3 * 64 * 65;

    const int tid = threadIdx.x;
    const int tx  = tid & 15;
    const int ty  = tid >> 4;
    const int qt  = blockIdx.x;
    const int h   = blockIdx.y;
    const int b   = blockIdx.z;
    const size_t base = ((size_t)b * NH + h) * S_ * HD;
    const float* Qb = Q + base;
    const float* Kb = K + base;
    const float* Vb = V + base;
    const int q0 = qt * 64;

#pragma unroll
    for (int it = 0; it < 4; it++) {
        const int idx = tid + it * 256;
        const int r   = idx >> 4;
        const int c4  = (idx & 15) << 2;
        const float4 qv = *(const float4*)(Qb + (size_t)(q0 + r) * HD + c4);
        Qs[(c4 + 0) * 65 + r] = qv.x;  Qs[(c4 + 1) * 65 + r] = qv.y;
        Qs[(c4 + 2) * 65 + r] = qv.z;  Qs[(c4 + 3) * 65 + r] = qv.w;
    }

    float m_i[4], l_i[4], o[4][4];
#pragma unroll
    for (int i = 0; i < 4; i++) {
        m_i[i] = -1e30f; l_i[i] = 0.f;
#pragma unroll
        for (int j = 0; j < 4; j++) o[i][j] = 0.f;
    }

    for (int kt = 0; kt <= qt; kt++) {
        __syncthreads();
#pragma unroll
        for (int it = 0; it < 4; it++) {
            const int idx = tid + it * 256;
            const int r   = idx >> 4;
            const int c4  = (idx & 15) << 2;
            const float4 kv = *(const float4*)(Kb + (size_t)(kt * 64 + r) * HD + c4);
            Ks[(c4 + 0) * 65 + r] = kv.x;  Ks[(c4 + 1) * 65 + r] = kv.y;
            Ks[(c4 + 2) * 65 + r] = kv.z;  Ks[(c4 + 3) * 65 + r] = kv.w;
            const float4 vv = *(const float4*)(Vb + (size_t)(kt * 64 + r) * HD + c4);
            Vs[r * 65 + c4 + 0] = vv.x;  Vs[r * 65 + c4 + 1] = vv.y;
            Vs[r * 65 + c4 + 2] = vv.z;  Vs[r * 65 + c4 + 3] = vv.w;
        }
        __syncthreads();

        float s[4][4];
#pragma unroll
        for (int i = 0; i < 4; i++)
#pragma unroll
            for (int j = 0; j < 4; j++) s[i][j] = 0.f;

#pragma unroll 8
        for (int d = 0; d < 64; d++) {
            float qf[4], kf[4];
#pragma unroll
            for (int i = 0; i < 4; i++) qf[i] = Qs[d * 65 + ty * 4 + i];
#pragma unroll
            for (int j = 0; j < 4; j++) kf[j] = Ks[d * 65 + tx * 4 + j];
#pragma unroll
            for (int i = 0; i < 4; i++)
#pragma unroll
                for (int j = 0; j < 4; j++)
                    s[i][j] += qf[i] * kf[j];
        }

        if (kt == qt) {
#pragma unroll
            for (int i = 0; i < 4; i++)
#pragma unroll
                for (int j = 0; j < 4; j++)
                    s[i][j] = (tx * 4 + j > ty * 4 + i) ? -1e30f : s[i][j] * SCALE_;
        } else {
#pragma unroll
            for (int i = 0; i < 4; i++)
#pragma unroll
                for (int j = 0; j < 4; j++)
                    s[i][j] *= SCALE_;
        }

#pragma unroll
        for (int i = 0; i < 4; i++) {
            float mx = fmaxf(fmaxf(s[i][0], s[i][1]), fmaxf(s[i][2], s[i][3]));
#pragma unroll
            for (int off = 1; off < 16; off <<= 1)
                mx = fmaxf(mx, __shfl_xor_sync(0xffffffffu, mx, off));
            const float mnew  = fmaxf(m_i[i], mx);
            const float alpha = __expf(m_i[i] - mnew);
            m_i[i] = mnew;
            float sum = 0.f;
#pragma unroll
            for (int j = 0; j < 4; j++) {
                const float p = __expf(s[i][j] - mnew);
                s[i][j] = p;
                sum += p;
            }
#pragma unroll
            for (int off = 1; off < 16; off <<= 1)
                sum += __shfl_xor_sync(0xffffffffu, sum, off);
            l_i[i] = l_i[i] * alpha + sum;
#pragma unroll
            for (int j = 0; j < 4; j++) o[i][j] *= alpha;
        }

#pragma unroll
        for (int i = 0; i < 4; i++)
#pragma unroll
            for (int j = 0; j < 4; j++)
                Ps[(tx * 4 + j) * 65 + ty * 4 + i] = s[i][j];
        __syncthreads();

#pragma unroll 8
        for (int kk = 0; kk < 64; kk++) {
            float pf[4], vf[4];
#pragma unroll
            for (int i = 0; i < 4; i++) pf[i] = Ps[kk * 65 + ty * 4 + i];
#pragma unroll
            for (int j = 0; j < 4; j++) vf[j] = Vs[kk * 65 + tx * 4 + j];
#pragma unroll
            for (int i = 0; i < 4; i++)
#pragma unroll
                for (int j = 0; j < 4; j++)
                    o[i][j] += pf[i] * vf[j];
        }
    }

#pragma unroll
    for (int i = 0; i < 4; i++) {
        const float inv = 1.f / l_i[i];
        const int srow = q0 + ty * 4 + i;
#pragma unroll
        for (int j = 0; j < 4; j++)
            Out[((size_t)b * S_ + srow) * HID + h * HD + tx * 4 + j] = o[i][j] * inv;
    }
}

// ---------------------------------------------------------------------------
// Launch (graph-capturable, allocation-free)
// ---------------------------------------------------------------------------
extern "C" void kernel_launch(void* const* d_in, const int* in_sizes, int n_in,
                              void* d_out, int out_size)
{
    const float* hidden = (const float*)d_in[0];
    const float* w_down = (const float*)d_in[1];
    const float* w_q_up = (const float*)d_in[2];
    const float* w_k_up = (const float*)d_in[3];
    const float* w_v_up = (const float*)d_in[4];
    const float* w_out  = (const float*)d_in[5];
    float* out = (float*)d_out;

    float *comp, *q, *k, *v, *attn;
    __nv_bfloat16 *ahi, *alo, *bhi, *blo;
    cudaGetSymbolAddress((void**)&comp, g_comp);
    cudaGetSymbolAddress((void**)&q,    g_q);
    cudaGetSymbolAddress((void**)&k,    g_k);
    cudaGetSymbolAddress((void**)&v,    g_v);
    cudaGetSymbolAddress((void**)&attn, g_attn);
    cudaGetSymbolAddress((void**)&ahi,  g_ahi);
    cudaGetSymbolAddress((void**)&alo,  g_alo);
    cudaGetSymbolAddress((void**)&bhi,  g_bhi);
    cudaGetSymbolAddress((void**)&blo,  g_blo);

    const int ATTN_SMEM = 4 * 64 * 65 * (int)sizeof(float);
    cudaFuncSetAttribute(attn_k,    cudaFuncAttributeMaxDynamicSharedMemorySize, ATTN_SMEM);
    cudaFuncSetAttribute(tc_gemm_k, cudaFuncAttributeMaxDynamicSharedMemorySize, GEMM_SMEM);

    const dim3 gg(HID / 128, MTOT / 128);   // (16, 32)
    const dim3 wt(32, 8);

    // 1) comp = hidden @ w_down
    split_a_k<<<1024, 256>>>(hidden, HID, HID, ahi, alo);
    wsplitT_k<<<dim3(HID / 32, HID / 32), wt>>>(w_down, HID, HID, bhi, blo);
    tc_gemm_k<<<gg, 256, GEMM_SMEM>>>(ahi, alo, bhi, blo, comp, HID, 0);

    // 2) Q = q_c @ w_q_up -> [B,H,S,D]
    split_a_k<<<1024, 256>>>(comp, HID, QC, ahi, alo);
    wsplitT_k<<<dim3(HID / 32, QC / 32), wt>>>(w_q_up, QC, HID, bhi, blo);
    tc_gemm_k<<<gg, 256, GEMM_SMEM>>>(ahi, alo, bhi, blo, q, QC, 1);

    // 3) K = k_c @ w_k_up -> [B,H,S,D]
    split_a_k<<<1024, 256>>>(comp + QC, HID, KVC, ahi, alo);
    wsplitT_k<<<dim3(HID / 32, KVC / 32), wt>>>(w_k_up, KVC, HID, bhi, blo);
    tc_gemm_k<<<gg, 256, GEMM_SMEM>>>(ahi, alo, bhi, blo, k, KVC, 1);

    // 4) V = v_c @ w_v_up -> [B,H,S,D]
    split_a_k<<<1024, 256>>>(comp + QC + KVC, HID, KVC, ahi, alo);
    wsplitT_k<<<dim3(HID / 32, KVC / 32), wt>>>(w_v_up, KVC, HID, bhi, blo);
    tc_gemm_k<<<gg, 256, GEMM_SMEM>>>(ahi, alo, bhi, blo, v, KVC, 1);

    // 5) causal flash attention -> [B,S,HID]
    attn_k<<<dim3(S_ / 64, NH, B_), 256, ATTN_SMEM>>>(q, k, v, attn);

    // 6) out = attn @ w_out
    split_a_k<<<1024, 256>>>(attn, HID, HID, ahi, alo);
    wsplitT_k<<<dim3(HID / 32, HID / 32), wt>>>(w_out, HID, HID, bhi, blo);
    tc_gemm_k<<<gg, 256, GEMM_SMEM>>>(ahi, alo, bhi, blo, out, HID, 0);
}